// round 8
// baseline (speedup 1.0000x reference)
#include <cuda_runtime.h>
#include <cstdint>

#define N_EDGES 3200000
#define N_NODES 100000
#define TPB 256
#define TILES 4
#define EPB (TPB * TILES)   // 1024 edges per block

// 16B-aligned padded copy of pos: one LDG.128 per gather instead of 3 LDG.32.
__device__ float4 g_pos_pad[N_NODES];

__global__ __launch_bounds__(256)
void pos_pad_kernel(const float* __restrict__ pos)
{
    const int i = blockIdx.x * blockDim.x + threadIdx.x;
    if (i < N_NODES) {
        g_pos_pad[i] = make_float4(pos[i * 3 + 0], pos[i * 3 + 1], pos[i * 3 + 2], 0.0f);
    }
}

__device__ __forceinline__ void mbar_wait(uint32_t mbar, uint32_t parity)
{
    uint32_t done;
    asm volatile(
        "{\n\t"
        ".reg .pred p;\n\t"
        "mbarrier.try_wait.parity.acquire.cta.shared::cta.b64 p, [%1], %2;\n\t"
        "selp.b32 %0, 1, 0, p;\n\t"
        "}"
        : "=r"(done) : "r"(mbar), "r"(parity) : "memory");
    if (!done) {
        asm volatile(
            "{\n\t"
            ".reg .pred P1;\n\t"
            "WAIT_LOOP_%=:\n\t"
            "mbarrier.try_wait.parity.acquire.cta.shared::cta.b64 P1, [%0], %1, 0x989680;\n\t"
            "@P1 bra.uni WAIT_DONE_%=;\n\t"
            "bra.uni WAIT_LOOP_%=;\n\t"
            "WAIT_DONE_%=:\n\t"
            "}"
            :: "r"(mbar), "r"(parity) : "memory");
    }
}

__device__ __forceinline__ void bulk_load_shift(float* sdst_f, const float* gsrc, uint32_t mbar)
{
    asm volatile("mbarrier.arrive.expect_tx.shared.b64 _, [%0], %1;"
                 :: "r"(mbar), "r"((unsigned)(TPB * 3 * 4)) : "memory");
    const uint32_t sdst = (uint32_t)__cvta_generic_to_shared(sdst_f);
    asm volatile(
        "cp.async.bulk.shared::cta.global.mbarrier::complete_tx::bytes [%0], [%1], %2, [%3];"
        :: "r"(sdst), "l"(gsrc), "r"((unsigned)(TPB * 3 * 4)), "r"(mbar)
        : "memory");
}

__global__ __launch_bounds__(256)
void sh_edge_attrs_kernel(const void* __restrict__ edge_index_raw,
                          const float* __restrict__ shift,
                          float* __restrict__ out)
{
    __shared__ alignas(16) float s_shift[2][TPB * 3];   // 2 x 3072 B
    __shared__ alignas(16) float s_vec[2][TPB * 3];     // 2 x 3072 B
    __shared__ alignas(16) float s_sh[2][TPB * 9];      // 2 x 9216 B
    __shared__ alignas(8)  unsigned long long s_mbar[2];

    const int t = threadIdx.x;
    const long long blk_base = (long long)blockIdx.x * EPB;

    const uint32_t mbar0 = (uint32_t)__cvta_generic_to_shared(&s_mbar[0]);
    const uint32_t mbar1 = (uint32_t)__cvta_generic_to_shared(&s_mbar[1]);

    if (t == 0) {
        asm volatile("mbarrier.init.shared.b64 [%0], 1;" :: "r"(mbar0) : "memory");
        asm volatile("mbarrier.init.shared.b64 [%0], 1;" :: "r"(mbar1) : "memory");
    }
    __syncthreads();

    // Prologue: prefetch shift tiles 0 and 1
    if (t == 0) {
        bulk_load_shift(s_shift[0], shift + blk_base * 3, mbar0);
        bulk_load_shift(s_shift[1], shift + (blk_base + TPB) * 3, mbar1);
    }

    // dtype probe: int64 indices (<2^32) have zero high halves
    const unsigned long long* p64 = (const unsigned long long*)edge_index_raw;
    const bool is64 = (((p64[0] | p64[1] | p64[2] | p64[3]) >> 32) == 0ULL);

    const float SQRT3 = 1.7320508075688772f;
    const float SQRT5 = 2.2360679774997896f;

#pragma unroll
    for (int k = 0; k < TILES; k++) {
        const int buf = k & 1;
        const uint32_t mbar   = buf ? mbar1 : mbar0;
        const uint32_t parity = (k >> 1) & 1;
        const long long tile_base = blk_base + (long long)k * TPB;
        const long long e = tile_base + t;

        // indices + gathers in flight before the mbar wait
        int src, dst;
        if (is64) {
            const long long* ei = (const long long*)edge_index_raw;
            src = (int)ei[e];
            dst = (int)ei[N_EDGES + e];
        } else {
            const int* ei = (const int*)edge_index_raw;
            src = ei[e];
            dst = ei[N_EDGES + e];
        }
        src = min(N_NODES - 1, max(0, src));
        dst = min(N_NODES - 1, max(0, dst));

        const float4 pd = __ldg(&g_pos_pad[dst]);
        const float4 ps = __ldg(&g_pos_pad[src]);

        mbar_wait(mbar, parity);

        const float sx = s_shift[buf][t * 3 + 0];
        const float sy = s_shift[buf][t * 3 + 1];
        const float sz = s_shift[buf][t * 3 + 2];

        const float vx = pd.x - ps.x - sx;
        const float vy = pd.y - ps.y - sy;
        const float vz = pd.z - ps.z - sz;

        const float n2   = vx * vx + vy * vy + vz * vz;
        const float rinv = rsqrtf(n2);
        const float len  = n2 * rinv;

        const float x = vx * rinv;
        const float y = vy * rinv;
        const float z = vz * rinv;
        const float x2 = x * x, y2 = y * y, z2 = z * z;

        // len: layout already coalesced -> direct store, no staging
        out[3LL * N_EDGES + e] = len;

        // free output buffer `buf` (store of tile k-2 must be complete),
        // and make sure every warp finished reading s_shift[buf] before we
        // re-arm it below.
        if (t == 0) {
            asm volatile("cp.async.bulk.wait_group %0;" :: "n"(1) : "memory");
        }
        __syncthreads();

        // prefetch shift for tile k+2 into the buffer we just vacated
        if (t == 0 && k + 2 < TILES) {
            bulk_load_shift(s_shift[buf], shift + (tile_base + 2 * TPB) * 3, mbar);
        }

        // stage vec + sh
        s_vec[buf][t * 3 + 0] = vx;
        s_vec[buf][t * 3 + 1] = vy;
        s_vec[buf][t * 3 + 2] = vz;

        float* shl = s_sh[buf] + t * 9;
        shl[0] = 1.0f;
        shl[1] = SQRT3 * x;
        shl[2] = SQRT3 * y;
        shl[3] = SQRT3 * z;
        shl[4] = SQRT5 * (SQRT3 * x * z);
        shl[5] = SQRT5 * (SQRT3 * x * y);
        shl[6] = SQRT5 * (y2 - 0.5f * (x2 + z2));
        shl[7] = SQRT5 * (SQRT3 * y * z);
        shl[8] = SQRT5 * (0.5f * SQRT3 * (z2 - x2));

        __syncthreads();

        if (t == 0) {
            asm volatile("fence.proxy.async.shared::cta;" ::: "memory");
            const uint32_t svec = (uint32_t)__cvta_generic_to_shared(s_vec[buf]);
            const uint32_t ssh  = (uint32_t)__cvta_generic_to_shared(s_sh[buf]);
            float* gvec = out + tile_base * 3;
            float* gsh  = out + 4LL * N_EDGES + tile_base * 9;
            asm volatile("cp.async.bulk.global.shared::cta.bulk_group [%0], [%1], %2;"
                         :: "l"(gvec), "r"(svec), "r"((unsigned)(TPB * 3 * 4)) : "memory");
            asm volatile("cp.async.bulk.global.shared::cta.bulk_group [%0], [%1], %2;"
                         :: "l"(gsh), "r"(ssh), "r"((unsigned)(TPB * 9 * 4)) : "memory");
            asm volatile("cp.async.bulk.commit_group;" ::: "memory");
        }
    }

    // drain all outstanding stores before smem is released
    if (t == 0) {
        asm volatile("cp.async.bulk.wait_group %0;" :: "n"(0) : "memory");
    }
}

extern "C" void kernel_launch(void* const* d_in, const int* in_sizes, int n_in,
                              void* d_out, int out_size)
{
    // Identify inputs by element count (robust to metadata ordering):
    //   pos: 300000 floats, edge_index: 6400000 ints, shift: 9600000 floats
    const float* pos        = nullptr;
    const void*  edge_index = nullptr;
    const float* shift      = nullptr;

    for (int i = 0; i < n_in; i++) {
        if (in_sizes[i] == 3 * N_NODES)      pos        = (const float*)d_in[i];
        else if (in_sizes[i] == 2 * N_EDGES) edge_index = (const void*)d_in[i];
        else if (in_sizes[i] == 3 * N_EDGES) shift      = (const float*)d_in[i];
    }

    float* out = (float*)d_out;

    pos_pad_kernel<<<(N_NODES + 255) / 256, 256>>>(pos);

    const int blocks = N_EDGES / EPB;   // 3125, exact
    sh_edge_attrs_kernel<<<blocks, TPB>>>(edge_index, shift, out);
}

// round 9
// speedup vs baseline: 1.2570x; 1.2570x over previous
#include <cuda_runtime.h>
#include <cstdint>

#define N_EDGES 3200000
#define N_NODES 100000
#define TPB 256

// 16B-aligned padded copy of pos: one LDG.128 per gather instead of 3 LDG.32.
__device__ float4 g_pos_pad[N_NODES];

// Vectorized pad: 256 nodes per block. 192 threads load 192 float4 (=768
// floats = 256 nodes) coalesced into smem; 256 threads write one padded
// float4 each (stride-3 LDS is conflict-free, STG fully coalesced).
__global__ __launch_bounds__(256)
void pos_pad_kernel(const float4* __restrict__ pos4)
{
    __shared__ float s[768];
    const int t = threadIdx.x;
    const int base_node = blockIdx.x * 256;
    const int base_f4   = blockIdx.x * 192;

    if (t < 192) {
        const int idx = base_f4 + t;
        if (idx < (3 * N_NODES) / 4) ((float4*)s)[t] = pos4[idx];
    }
    __syncthreads();

    const int node = base_node + t;
    if (node < N_NODES) {
        g_pos_pad[node] = make_float4(s[t * 3 + 0], s[t * 3 + 1], s[t * 3 + 2], 0.0f);
    }
}

__global__ __launch_bounds__(256)
void sh_edge_attrs_kernel(const void* __restrict__ edge_index_raw,
                          const float* __restrict__ shift,
                          float* __restrict__ out)
{
    __shared__ alignas(16) float s_shift[TPB * 3];            // 3072 B
    __shared__ alignas(16) float s_vec[TPB * 3];              // 3072 B
    __shared__ alignas(16) float s_sh[TPB * 9];               // 9216 B
    __shared__ alignas(8)  unsigned long long s_mbar;

    const int t = threadIdx.x;
    const long long blk_base = (long long)blockIdx.x * TPB;

    const uint32_t mbar = (uint32_t)__cvta_generic_to_shared(&s_mbar);

    if (t == 0) {
        asm volatile("mbarrier.init.shared.b64 [%0], 1;" :: "r"(mbar) : "memory");
    }
    __syncthreads();

    // ---- async bulk load of this block's shift tile (bypasses L1 wavefronts) ----
    if (t == 0) {
        asm volatile("mbarrier.arrive.expect_tx.shared.b64 _, [%0], %1;"
                     :: "r"(mbar), "r"((unsigned)(TPB * 3 * 4)) : "memory");
        const uint32_t sdst = (uint32_t)__cvta_generic_to_shared(s_shift);
        asm volatile(
            "cp.async.bulk.shared::cta.global.mbarrier::complete_tx::bytes [%0], [%1], %2, [%3];"
            :: "r"(sdst), "l"(shift + blk_base * 3), "r"((unsigned)(TPB * 3 * 4)), "r"(mbar)
            : "memory");
    }

    // ---- edge indices (dtype probe: int64 values < 2^32 have zero high halves) ----
    const unsigned long long* p64 = (const unsigned long long*)edge_index_raw;
    const bool is64 = (((p64[0] | p64[1] | p64[2] | p64[3]) >> 32) == 0ULL);

    const long long e = blk_base + t;
    int src, dst;
    if (is64) {
        const long long* ei = (const long long*)edge_index_raw;
        src = (int)ei[e];
        dst = (int)ei[N_EDGES + e];
    } else {
        const int* ei = (const int*)edge_index_raw;
        src = ei[e];
        dst = ei[N_EDGES + e];
    }
    src = min(N_NODES - 1, max(0, src));
    dst = min(N_NODES - 1, max(0, dst));

    // ---- pos gathers: single 16B load per node, in flight during the bulk load ----
    const float4 pd = __ldg(&g_pos_pad[dst]);
    const float4 ps = __ldg(&g_pos_pad[src]);

    // ---- wait for shift tile ----
    {
        uint32_t done;
        asm volatile(
            "{\n\t"
            ".reg .pred p;\n\t"
            "mbarrier.try_wait.parity.acquire.cta.shared::cta.b64 p, [%1], 0;\n\t"
            "selp.b32 %0, 1, 0, p;\n\t"
            "}"
            : "=r"(done) : "r"(mbar) : "memory");
        if (!done) {
            asm volatile(
                "{\n\t"
                ".reg .pred P1;\n\t"
                "WAIT_LOOP_%=:\n\t"
                "mbarrier.try_wait.parity.acquire.cta.shared::cta.b64 P1, [%0], 0, 0x989680;\n\t"
                "@P1 bra.uni WAIT_DONE_%=;\n\t"
                "bra.uni WAIT_LOOP_%=;\n\t"
                "WAIT_DONE_%=:\n\t"
                "}"
                :: "r"(mbar) : "memory");
        }
    }

    const float sx = s_shift[t * 3 + 0];
    const float sy = s_shift[t * 3 + 1];
    const float sz = s_shift[t * 3 + 2];

    const float vx = pd.x - ps.x - sx;
    const float vy = pd.y - ps.y - sy;
    const float vz = pd.z - ps.z - sz;

    const float n2   = vx * vx + vy * vy + vz * vz;
    const float rinv = rsqrtf(n2);
    const float len  = n2 * rinv;

    const float x = vx * rinv;
    const float y = vy * rinv;
    const float z = vz * rinv;

    const float SQRT3 = 1.7320508075688772f;
    const float SQRT5 = 2.2360679774997896f;
    const float x2 = x * x, y2 = y * y, z2 = z * z;

    // len layout is already coalesced: direct store, no staging
    out[3LL * N_EDGES + e] = len;

    // ---- stage results (odd strides -> bank-conflict-free) ----
    s_vec[t * 3 + 0] = vx;
    s_vec[t * 3 + 1] = vy;
    s_vec[t * 3 + 2] = vz;

    float* shl = s_sh + t * 9;
    shl[0] = 1.0f;
    shl[1] = SQRT3 * x;
    shl[2] = SQRT3 * y;
    shl[3] = SQRT3 * z;
    shl[4] = SQRT5 * (SQRT3 * x * z);
    shl[5] = SQRT5 * (SQRT3 * x * y);
    shl[6] = SQRT5 * (y2 - 0.5f * (x2 + z2));
    shl[7] = SQRT5 * (SQRT3 * y * z);
    shl[8] = SQRT5 * (0.5f * SQRT3 * (z2 - x2));

    __syncthreads();

    // ---- async bulk stores: TMA reads smem directly, no L1 wavefronts ----
    if (t == 0) {
        asm volatile("fence.proxy.async.shared::cta;" ::: "memory");

        const uint32_t svec = (uint32_t)__cvta_generic_to_shared(s_vec);
        const uint32_t ssh  = (uint32_t)__cvta_generic_to_shared(s_sh);

        float* gvec = out + blk_base * 3;
        float* gsh  = out + 4LL * N_EDGES + blk_base * 9;

        asm volatile("cp.async.bulk.global.shared::cta.bulk_group [%0], [%1], %2;"
                     :: "l"(gvec), "r"(svec), "r"((unsigned)(TPB * 3 * 4)) : "memory");
        asm volatile("cp.async.bulk.global.shared::cta.bulk_group [%0], [%1], %2;"
                     :: "l"(gsh), "r"(ssh), "r"((unsigned)(TPB * 9 * 4)) : "memory");
        asm volatile("cp.async.bulk.commit_group;" ::: "memory");
        asm volatile("cp.async.bulk.wait_group 0;" ::: "memory");
    }
}

extern "C" void kernel_launch(void* const* d_in, const int* in_sizes, int n_in,
                              void* d_out, int out_size)
{
    // Identify inputs by element count (robust to metadata ordering):
    //   pos: 300000 floats, edge_index: 6400000 ints, shift: 9600000 floats
    const float* pos        = nullptr;
    const void*  edge_index = nullptr;
    const float* shift      = nullptr;

    for (int i = 0; i < n_in; i++) {
        if (in_sizes[i] == 3 * N_NODES)      pos        = (const float*)d_in[i];
        else if (in_sizes[i] == 2 * N_EDGES) edge_index = (const void*)d_in[i];
        else if (in_sizes[i] == 3 * N_EDGES) shift      = (const float*)d_in[i];
    }

    float* out = (float*)d_out;

    const int pad_blocks = (N_NODES + 255) / 256;   // 391
    pos_pad_kernel<<<pad_blocks, 256>>>((const float4*)pos);

    const int blocks = N_EDGES / TPB;   // 12500, exact
    sh_edge_attrs_kernel<<<blocks, TPB>>>(edge_index, shift, out);
}